// round 8
// baseline (speedup 1.0000x reference)
#include <cuda_runtime.h>
#include <cuda_fp16.h>
#include <math.h>

// Problem constants
#define Bb 2
#define Ss 2048
#define DM 1024
#define Hh 16
#define DKh 64
#define MTOK (Bb*Ss)                 // 4096
#define OUT_ELEMS ((size_t)Bb*Ss*DM)

#define SCALE_L2E 0.18033688011112042f   // 0.125 * log2(e)

typedef unsigned int u32;
typedef unsigned short u16;
typedef unsigned long long u64;

// ---------------- device scratch ----------------
__device__ __half g_qi_h[MTOK*DM], g_qi_l[MTOK*DM];
__device__ __half g_ki_h[MTOK*DM], g_ki_l[MTOK*DM];
__device__ __half g_vi_h[MTOK*DM], g_vi_l[MTOK*DM];
__device__ __half g_wq_h[DM*DM], g_wq_l[DM*DM];
__device__ __half g_wk_h[DM*DM], g_wk_l[DM*DM];
__device__ __half g_wv_h[DM*DM], g_wv_l[DM*DM];
__device__ __half g_wo_h[DM*DM], g_wo_l[DM*DM];
__device__ __half g_qh_h[MTOK*DM], g_qh_l[MTOK*DM];
__device__ __half g_kh_h[MTOK*DM], g_kh_l[MTOK*DM];
__device__ __half g_vh_h[MTOK*DM];
__device__ __half g_oh_h[MTOK*DM], g_oh_l[MTOK*DM];
__device__ float  g_y[MTOK*DM];
__device__ u64    g_mbits[(size_t)Bb*Ss*(Ss/64)];   // 1 bit per mask byte

// ---------------- helpers ----------------
__device__ __forceinline__ u32 smaddr(const void* p) {
    return (u32)__cvta_generic_to_shared(p);
}
__device__ __forceinline__ void ldsm4(u32& r0, u32& r1, u32& r2, u32& r3, u32 a) {
    asm volatile("ldmatrix.sync.aligned.m8n8.x4.shared.b16 {%0,%1,%2,%3},[%4];"
                 : "=r"(r0), "=r"(r1), "=r"(r2), "=r"(r3) : "r"(a));
}
__device__ __forceinline__ void ldsm4t(u32& r0, u32& r1, u32& r2, u32& r3, u32 a) {
    asm volatile("ldmatrix.sync.aligned.m8n8.x4.trans.shared.b16 {%0,%1,%2,%3},[%4];"
                 : "=r"(r0), "=r"(r1), "=r"(r2), "=r"(r3) : "r"(a));
}
__device__ __forceinline__ void mma16(float* d, const u32* a, u32 b0, u32 b1) {
    asm volatile(
        "mma.sync.aligned.m16n8k16.row.col.f32.f16.f16.f32 "
        "{%0,%1,%2,%3},{%4,%5,%6,%7},{%8,%9},{%0,%1,%2,%3};"
        : "+f"(d[0]), "+f"(d[1]), "+f"(d[2]), "+f"(d[3])
        : "r"(a[0]), "r"(a[1]), "r"(a[2]), "r"(a[3]), "r"(b0), "r"(b1));
}
__device__ __forceinline__ void cpa16(u32 dst, const void* src) {
    asm volatile("cp.async.cg.shared.global [%0], [%1], 16;" :: "r"(dst), "l"(src));
}
#define CP_COMMIT() asm volatile("cp.async.commit_group;")
#define CP_WAIT1()  asm volatile("cp.async.wait_group 1;")
#define CP_WAIT0()  asm volatile("cp.async.wait_group 0;")
__device__ __forceinline__ float ex2f(float x) {
    float r; asm("ex2.approx.f32 %0, %1;" : "=f"(r) : "f"(x)); return r;
}

// ---------------- mask -> bitmask (1 bit per byte) ----------------
__global__ void __launch_bounds__(256)
mask_bits(const unsigned char* __restrict__ mask)
{
    int i = blockIdx.x * 256 + threadIdx.x;       // < Bb*Ss*32
    const u64* src = (const u64*)(mask + (size_t)i * 64);
    u64 bits = 0;
    #pragma unroll
    for (int c = 0; c < 8; ++c) {
        u64 w = src[c] & 0x0101010101010101ULL;
        bits |= ((w * 0x0102040810204080ULL) >> 56) << (c * 8);
    }
    g_mbits[i] = bits;
}

// ---------------- split kernels ----------------
__global__ void __launch_bounds__(256)
split_f32(const float* __restrict__ src, __half* __restrict__ dh,
          __half* __restrict__ dl, int n4)
{
    int i = blockIdx.x * 256 + threadIdx.x;
    if (i >= n4) return;
    float4 v = ((const float4*)src)[i];
    __half2 h0 = __floats2half2_rn(v.x, v.y);
    __half2 h1 = __floats2half2_rn(v.z, v.w);
    float2 f0 = __half22float2(h0), f1 = __half22float2(h1);
    ((__half2*)dh)[2*i]   = h0; ((__half2*)dh)[2*i+1] = h1;
    ((__half2*)dl)[2*i]   = __floats2half2_rn(v.x - f0.x, v.y - f0.y);
    ((__half2*)dl)[2*i+1] = __floats2half2_rn(v.z - f1.x, v.w - f1.y);
}

// W[K][N] -> T[N][K] split hi/lo
__global__ void __launch_bounds__(256)
splitT_w(const float* __restrict__ W, __half* __restrict__ th,
         __half* __restrict__ tl)
{
    __shared__ float t[32][33];
    int kb = blockIdx.y * 32, nb = blockIdx.x * 32;
    int tx = threadIdx.x, ty = threadIdx.y;
    #pragma unroll
    for (int i = 0; i < 4; ++i)
        t[ty + i*8][tx] = W[(size_t)(kb + ty + i*8) * DM + nb + tx];
    __syncthreads();
    #pragma unroll
    for (int i = 0; i < 4; ++i) {
        int n = nb + ty + i*8, k = kb + tx;
        float v = t[tx][ty + i*8];
        __half h = __float2half_rn(v);
        th[(size_t)n * DM + k] = h;
        tl[(size_t)n * DM + k] = __float2half_rn(v - __half2float(h));
    }
}

// ---------------------------------------------------------------------------
// fp16 3-term GEMM, cp.async double-buffered (unchanged from R6).
// ---------------------------------------------------------------------------
#define SG 40
#define GARR (128*SG)
#define GSTG (4*GARR)
__global__ void __launch_bounds__(256)
gemm_h3(const __half* __restrict__ Ah, const __half* __restrict__ Al,
        const __half* __restrict__ Bh, const __half* __restrict__ Bl,
        const float* __restrict__ bias, const float* __restrict__ R,
        float omul,
        __half* __restrict__ Ch, __half* __restrict__ Cl,
        float* __restrict__ Cf, int M, int N, int K)
{
    extern __shared__ __half dsm[];
    const int tid = threadIdx.x, lane = tid & 31, wid = tid >> 5;
    const int wm = wid & 3, wn = wid >> 2;
    const int bm = blockIdx.y * 128, bn = blockIdx.x * 128;
    float acc[2][8][4] = {};
    const int arow = lane & 15, achk = lane >> 4;
    const int brow = ((lane >> 4) << 3) + (lane & 7), bchk = (lane >> 3) & 1;
    const u32 smbase = smaddr(dsm);

    auto load_stage = [&](int st, int k0) {
        u32 base = smbase + (u32)st * GSTG * 2;
        #pragma unroll
        for (int i = 0; i < 2; ++i) {
            int e = tid + i * 256;
            int m = e >> 2, c = e & 3;
            size_t ga = (size_t)(bm + m) * K + k0 + c*8;
            size_t gb = (size_t)(bn + m) * K + k0 + c*8;
            u32 o = (u32)(m*SG + c*8) * 2;
            cpa16(base + 0*GARR*2 + o, Ah + ga);
            cpa16(base + 1*GARR*2 + o, Al + ga);
            cpa16(base + 2*GARR*2 + o, Bh + gb);
            cpa16(base + 3*GARR*2 + o, Bl + gb);
        }
        CP_COMMIT();
    };

    const int nk = K / 32;
    load_stage(0, 0);
    for (int kt = 0; kt < nk; ++kt) {
        if (kt + 1 < nk) { load_stage((kt+1)&1, (kt+1)*32); CP_WAIT1(); }
        else             { CP_WAIT0(); }
        __syncthreads();
        const u32 sAh = smbase + (u32)(kt&1)*GSTG*2;
        const u32 sAl = sAh + GARR*2;
        const u32 sBh = sAl + GARR*2;
        const u32 sBl = sBh + GARR*2;
        #pragma unroll
        for (int kc = 0; kc < 2; ++kc) {
            u32 ah[2][4], al[2][4];
            #pragma unroll
            for (int mt = 0; mt < 2; ++mt) {
                int row = wm*32 + mt*16 + arow;
                u32 off = row*(SG*2) + (2*kc + achk)*16;
                ldsm4(ah[mt][0],ah[mt][1],ah[mt][2],ah[mt][3], sAh+off);
                ldsm4(al[mt][0],al[mt][1],al[mt][2],al[mt][3], sAl+off);
            }
            #pragma unroll
            for (int ntp = 0; ntp < 4; ++ntp) {
                int row = wn*64 + ntp*16 + brow;
                u32 off = row*(SG*2) + (2*kc + bchk)*16;
                u32 b0,b1,b2,b3, c0,c1,c2,c3;
                ldsm4(b0,b1,b2,b3, sBh+off);
                ldsm4(c0,c1,c2,c3, sBl+off);
                #pragma unroll
                for (int mt = 0; mt < 2; ++mt) {
                    mma16(acc[mt][2*ntp],   ah[mt], b0, b1);
                    mma16(acc[mt][2*ntp],   al[mt], b0, b1);
                    mma16(acc[mt][2*ntp],   ah[mt], c0, c1);
                    mma16(acc[mt][2*ntp+1], ah[mt], b2, b3);
                    mma16(acc[mt][2*ntp+1], al[mt], b2, b3);
                    mma16(acc[mt][2*ntp+1], ah[mt], c2, c3);
                }
            }
        }
        __syncthreads();
    }

    #pragma unroll
    for (int mt = 0; mt < 2; ++mt) {
        int r0 = bm + wm*32 + mt*16 + (lane >> 2);
        #pragma unroll
        for (int nt = 0; nt < 8; ++nt) {
            int n = bn + wn*64 + nt*8 + (lane & 3)*2;
            float2 bs = *(const float2*)&bias[n];
            float* d = acc[mt][nt];
            float v00 = (d[0]+bs.x)*omul, v01 = (d[1]+bs.y)*omul;
            float v10 = (d[2]+bs.x)*omul, v11 = (d[3]+bs.y)*omul;
            if (Cf) {
                float2 ra = *(const float2*)&R[(size_t)r0*N + n];
                float2 rb = *(const float2*)&R[(size_t)(r0+8)*N + n];
                *(float2*)&Cf[(size_t)r0*N + n]     = make_float2(v00+ra.x, v01+ra.y);
                *(float2*)&Cf[(size_t)(r0+8)*N + n] = make_float2(v10+rb.x, v11+rb.y);
            } else if (Cl) {
                __half2 h0 = __floats2half2_rn(v00, v01);
                __half2 h1 = __floats2half2_rn(v10, v11);
                float2 f0 = __half22float2(h0), f1 = __half22float2(h1);
                *(__half2*)&Ch[(size_t)r0*N + n]     = h0;
                *(__half2*)&Ch[(size_t)(r0+8)*N + n] = h1;
                *(__half2*)&Cl[(size_t)r0*N + n]     = __floats2half2_rn(v00-f0.x, v01-f0.y);
                *(__half2*)&Cl[(size_t)(r0+8)*N + n] = __floats2half2_rn(v10-f1.x, v11-f1.y);
            } else {
                *(__half2*)&Ch[(size_t)r0*N + n]     = __floats2half2_rn(v00, v01);
                *(__half2*)&Ch[(size_t)(r0+8)*N + n] = __floats2half2_rn(v10, v11);
            }
        }
    }
}

// ---------------------------------------------------------------------------
// Single-pass attention. Block = 32 q-rows x full 2048 k, one (b,h).
// QK 3-term -> p_un = 2^(s-8) -> p16 kept in smem S_tile; rowsum + PV
// (unnormalized) accumulated in the same sweep. Epilogue: normalize P from
// smem (single write), normalize O in registers, cross-warp O reduce.
// ---------------------------------------------------------------------------
#define SP 72
#define S_STR 2056                       // 2048 + 8 halves (bank-conflict pad)
#define KSTG (64*SP)                     // 4608 halves per staging array
#define S_HALVES (32*S_STR)              // 65792
#define SMEM_ATTN ((S_HALVES + 6*KSTG)*2)   // 186880 bytes

__global__ void __launch_bounds__(256)
attn_single(float* __restrict__ P)
{
    extern __shared__ __half dsm[];
    __shared__ float sred[32][4];
    __shared__ float sinv[32];
    const int tid = threadIdx.x, lane = tid & 31, wid = tid >> 5;
    const int wm = wid & 1, wn = wid >> 1;          // 2 m-groups x 4 n-slices
    const int bh = blockIdx.y, b = bh >> 4, h = bh & 15;
    const int bq = blockIdx.x * 32;
    const int arow = lane & 15, achk = lane >> 4;
    const int brow = ((lane >> 4) << 3) + (lane & 7), bchk = (lane >> 3) & 1;

    __half* S_tile = dsm;
    const u32 smKh = smaddr(dsm) + S_HALVES*2;
    const u32 smKl = smKh + 2*KSTG*2;
    const u32 smVh = smKl + 2*KSTG*2;

    // ---- Q fragments (staged via Kh/Kl stage-0 buffers) ----
    for (int i = tid; i < 32*8; i += 256) {
        int m = i >> 3, ch = i & 7;
        size_t gq = (size_t)(b*Ss + bq + m)*DM + h*DKh + ch*8;
        *(uint4*)&dsm[S_HALVES + m*SP + ch*8]          = *(const uint4*)&g_qh_h[gq];
        *(uint4*)&dsm[S_HALVES + 2*KSTG + m*SP + ch*8] = *(const uint4*)&g_qh_l[gq];
    }
    __syncthreads();
    u32 qfh[4][4], qfl[4][4];
    {
        int row = wm*16 + arow;
        #pragma unroll
        for (int kc = 0; kc < 4; ++kc) {
            u32 off = row*(SP*2) + (2*kc + achk)*16;
            ldsm4(qfh[kc][0],qfh[kc][1],qfh[kc][2],qfh[kc][3], smKh + off);
            ldsm4(qfl[kc][0],qfl[kc][1],qfl[kc][2],qfl[kc][3], smKl + off);
        }
    }
    __syncthreads();

    auto load_stage = [&](int st, int kt) {
        #pragma unroll
        for (int i = 0; i < 2; ++i) {
            int e = tid + i*256;
            int m = e >> 3, ch = e & 7;
            size_t gk = (size_t)(b*Ss + kt*64 + m)*DM + h*DKh + ch*8;
            u32 o = (u32)(m*SP + ch*8)*2 + (u32)st*KSTG*2;
            cpa16(smKh + o, g_kh_h + gk);
            cpa16(smKl + o, g_kh_l + gk);
            cpa16(smVh + o, g_vh_h + gk);
        }
        CP_COMMIT();
    };

    const int r0 = wm*16 + (lane >> 2);     // block-local row
    const int r1 = r0 + 8;
    float rs0 = 0.f, rs1 = 0.f;
    float oacc[8][4] = {};

    load_stage(0, 0);
    for (int kt = 0; kt < 32; ++kt) {
        if (kt + 1 < 32) { load_stage((kt+1)&1, kt+1); CP_WAIT1(); }
        else             { CP_WAIT0(); }
        __syncthreads();
        const u32 sKh = smKh + (u32)(kt&1)*KSTG*2;
        const u32 sKl = smKl + (u32)(kt&1)*KSTG*2;
        const u32 sVh = smVh + (u32)(kt&1)*KSTG*2;

        // QK 3-term for this warp's 16 kv cols
        float sf[2][4] = {};
        #pragma unroll
        for (int kc = 0; kc < 4; ++kc) {
            u32 off = (wn*16 + brow)*(SP*2) + (2*kc + bchk)*16;
            u32 b0,b1,b2,b3, c0,c1,c2,c3;
            ldsm4(b0,b1,b2,b3, sKh + off);
            ldsm4(c0,c1,c2,c3, sKl + off);
            mma16(sf[0], qfh[kc], b0, b1);
            mma16(sf[0], qfl[kc], b0, b1);
            mma16(sf[0], qfh[kc], c0, c1);
            mma16(sf[1], qfh[kc], b2, b3);
            mma16(sf[1], qfl[kc], b2, b3);
            mma16(sf[1], qfh[kc], c2, c3);
        }

        // p_un = 2^(s-8) (masked), p16 to smem + rowsum
        u64 mb0 = g_mbits[((size_t)b*Ss + bq + r0)*32 + kt];
        u64 mb1 = g_mbits[((size_t)b*Ss + bq + r1)*32 + kt];
        u32 aph[4];
        #pragma unroll
        for (int nt = 0; nt < 2; ++nt) {
            int sh = wn*16 + nt*8 + (lane & 3)*2;
            float p0 = ((mb0 >> sh) & 1)     ? 0.f : ex2f(sf[nt][0] - 8.0f);
            float p1 = ((mb0 >> (sh+1)) & 1) ? 0.f : ex2f(sf[nt][1] - 8.0f);
            float p2 = ((mb1 >> sh) & 1)     ? 0.f : ex2f(sf[nt][2] - 8.0f);
            float p3 = ((mb1 >> (sh+1)) & 1) ? 0.f : ex2f(sf[nt][3] - 8.0f);
            rs0 += p0 + p1;  rs1 += p2 + p3;
            __half2 h01 = __floats2half2_rn(p0, p1);
            __half2 h23 = __floats2half2_rn(p2, p3);
            int col = kt*64 + sh;
            *(__half2*)&S_tile[r0*S_STR + col] = h01;
            *(__half2*)&S_tile[r1*S_STR + col] = h23;
            aph[2*nt]   = *(u32*)&h01;
            aph[2*nt+1] = *(u32*)&h23;
        }

        // PV: O_un += p16 @ Vh over this warp's k16 slice
        {
            int vrow = wn*16 + ((lane >> 3) & 1)*8 + (lane & 7);
            #pragma unroll
            for (int ntv = 0; ntv < 4; ++ntv) {
                int dch = ntv*16 + (lane >> 4)*8;
                u32 off = vrow*(SP*2) + dch*2;
                u32 v0,v1,v2,v3;
                ldsm4t(v0,v1,v2,v3, sVh + off);
                mma16(oacc[2*ntv],   aph, v0, v1);
                mma16(oacc[2*ntv+1], aph, v2, v3);
            }
        }
        __syncthreads();
    }

    // ---- rowsum reduce (quad lanes, then 4 wn warps) ----
    rs0 += __shfl_xor_sync(0xffffffffu, rs0, 1);
    rs0 += __shfl_xor_sync(0xffffffffu, rs0, 2);
    rs1 += __shfl_xor_sync(0xffffffffu, rs1, 1);
    rs1 += __shfl_xor_sync(0xffffffffu, rs1, 2);
    if ((lane & 3) == 0) {
        sred[r0][wn] = rs0;
        sred[r1][wn] = rs1;
    }
    __syncthreads();
    if (tid < 32)
        sinv[tid] = 1.0f / (sred[tid][0] + sred[tid][1] + sred[tid][2] + sred[tid][3]);
    __syncthreads();

    // ---- write normalized P from smem (the only P write) ----
    #pragma unroll
    for (int rr = 0; rr < 4; ++rr) {
        int r = wid*4 + rr;
        float inv = sinv[r];
        float* Pr = P + ((size_t)bh*Ss + bq + r)*Ss;
        #pragma unroll
        for (int j = 0; j < 8; ++j) {
            int col = lane*8 + j*256;
            uint4 u = *(uint4*)&S_tile[r*S_STR + col];
            __half2* hp = (__half2*)&u;
            float2 f0 = __half22float2(hp[0]);
            float2 f1 = __half22float2(hp[1]);
            float2 f2 = __half22float2(hp[2]);
            float2 f3 = __half22float2(hp[3]);
            *(float4*)&Pr[col]   = make_float4(f0.x*inv, f0.y*inv, f1.x*inv, f1.y*inv);
            *(float4*)&Pr[col+4] = make_float4(f2.x*inv, f2.y*inv, f3.x*inv, f3.y*inv);
        }
    }
    __syncthreads();

    // ---- O reduce across the 4 wn warps (reuse S_tile as float scratch) ----
    float* obuf = (float*)dsm;
    {
        int rb = lane >> 2;
        #pragma unroll
        for (int nt = 0; nt < 8; ++nt) {
            int d = nt*8 + (lane & 3)*2;
            obuf[wid*1024 + rb*64 + d]         = oacc[nt][0];
            obuf[wid*1024 + rb*64 + d + 1]     = oacc[nt][1];
            obuf[wid*1024 + (rb+8)*64 + d]     = oacc[nt][2];
            obuf[wid*1024 + (rb+8)*64 + d + 1] = oacc[nt][3];
        }
    }
    __syncthreads();
    for (int i = tid; i < 32*64; i += 256) {
        int r = i >> 6, d = i & 63;
        int wmr = r >> 4, rl = r & 15;
        float s = obuf[(0*2+wmr)*1024 + rl*64 + d]
                + obuf[(1*2+wmr)*1024 + rl*64 + d]
                + obuf[(2*2+wmr)*1024 + rl*64 + d]
                + obuf[(3*2+wmr)*1024 + rl*64 + d];
        s *= sinv[r];
        size_t gi = (size_t)(b*Ss + bq + r)*DM + h*DKh + d;
        __half hh = __float2half_rn(s);
        g_oh_h[gi] = hh;
        g_oh_l[gi] = __float2half_rn(s - __half2float(hh));
    }
}

// ---------------------------------------------------------------------------
// LayerNorm per row of 1024
// ---------------------------------------------------------------------------
__global__ void __launch_bounds__(256)
layernorm(const float* __restrict__ Xin, const float* __restrict__ gamma,
          const float* __restrict__ beta, float* __restrict__ out)
{
    const float* x = Xin + (size_t)blockIdx.x * DM;
    float* o = out + (size_t)blockIdx.x * DM;
    const int tid = threadIdx.x;
    __shared__ float r1[256], r2[256];

    float v[4], s = 0.f, sq = 0.f;
    #pragma unroll
    for (int i = 0; i < 4; ++i) {
        v[i] = x[tid + i * 256];
        s += v[i];
        sq += v[i] * v[i];
    }
    r1[tid] = s; r2[tid] = sq; __syncthreads();
    for (int st = 128; st > 0; st >>= 1) {
        if (tid < st) { r1[tid] += r1[tid + st]; r2[tid] += r2[tid + st]; }
        __syncthreads();
    }
    float mean = r1[0] * (1.0f / DM);
    float var  = r2[0] * (1.0f / DM) - mean * mean;
    float inv = rsqrtf(var + 1e-5f);
    #pragma unroll
    for (int i = 0; i < 4; ++i) {
        int c = tid + i * 256;
        o[c] = (v[i] - mean) * inv * gamma[c] + beta[c];
    }
}

// ---------------------------------------------------------------------------
extern "C" void kernel_launch(void* const* d_in, const int* in_sizes, int n_in,
                              void* d_out, int out_size)
{
    const float* q    = (const float*)d_in[0];
    const float* k    = (const float*)d_in[1];
    const float* v    = (const float*)d_in[2];
    const unsigned char* mask = (const unsigned char*)d_in[3];
    const float* Wq   = (const float*)d_in[4];
    const float* bq   = (const float*)d_in[5];
    const float* Wk   = (const float*)d_in[6];
    const float* bk   = (const float*)d_in[7];
    const float* Wv   = (const float*)d_in[8];
    const float* bv   = (const float*)d_in[9];
    const float* Wo   = (const float*)d_in[10];
    const float* bo   = (const float*)d_in[11];
    const float* ln_g = (const float*)d_in[12];
    const float* ln_b = (const float*)d_in[13];

    float* outp = (float*)d_out;
    float* attn = outp + OUT_ELEMS;

    __half *qi_h,*qi_l,*ki_h,*ki_l,*vi_h,*vi_l;
    __half *wq_h,*wq_l,*wk_h,*wk_l,*wv_h,*wv_l,*wo_h,*wo_l;
    __half *qh_h,*qh_l,*kh_h,*kh_l,*vh_h,*oh_h,*oh_l;
    float *y;
    cudaGetSymbolAddress((void**)&qi_h, g_qi_h); cudaGetSymbolAddress((void**)&qi_l, g_qi_l);
    cudaGetSymbolAddress((void**)&ki_h, g_ki_h); cudaGetSymbolAddress((void**)&ki_l, g_ki_l);
    cudaGetSymbolAddress((void**)&vi_h, g_vi_h); cudaGetSymbolAddress((void**)&vi_l, g_vi_l);
    cudaGetSymbolAddress((void**)&wq_h, g_wq_h); cudaGetSymbolAddress((void**)&wq_l, g_wq_l);
    cudaGetSymbolAddress((void**)&wk_h, g_wk_h); cudaGetSymbolAddress((void**)&wk_l, g_wk_l);
    cudaGetSymbolAddress((void**)&wv_h, g_wv_h); cudaGetSymbolAddress((void**)&wv_l, g_wv_l);
    cudaGetSymbolAddress((void**)&wo_h, g_wo_h); cudaGetSymbolAddress((void**)&wo_l, g_wo_l);
    cudaGetSymbolAddress((void**)&qh_h, g_qh_h); cudaGetSymbolAddress((void**)&qh_l, g_qh_l);
    cudaGetSymbolAddress((void**)&kh_h, g_kh_h); cudaGetSymbolAddress((void**)&kh_l, g_kh_l);
    cudaGetSymbolAddress((void**)&vh_h, g_vh_h);
    cudaGetSymbolAddress((void**)&oh_h, g_oh_h); cudaGetSymbolAddress((void**)&oh_l, g_oh_l);
    cudaGetSymbolAddress((void**)&y, g_y);

    static bool attr_done = false;
    const int GEMM_SMEM = 2 * GSTG * 2;
    if (!attr_done) {
        cudaFuncSetAttribute(gemm_h3, cudaFuncAttributeMaxDynamicSharedMemorySize, GEMM_SMEM);
        cudaFuncSetAttribute(attn_single, cudaFuncAttributeMaxDynamicSharedMemorySize, SMEM_ATTN);
        attr_done = true;
    }

    const int n4 = MTOK * DM / 4;
    split_f32<<<(n4+255)/256, 256>>>(q, qi_h, qi_l, n4);
    split_f32<<<(n4+255)/256, 256>>>(k, ki_h, ki_l, n4);
    split_f32<<<(n4+255)/256, 256>>>(v, vi_h, vi_l, n4);
    mask_bits<<<(Bb*Ss*32)/256, 256>>>(mask);

    dim3 gT(DM/32, DM/32), bT(32, 8);
    splitT_w<<<gT, bT>>>(Wq, wq_h, wq_l);
    splitT_w<<<gT, bT>>>(Wk, wk_h, wk_l);
    splitT_w<<<gT, bT>>>(Wv, wv_h, wv_l);
    splitT_w<<<gT, bT>>>(Wo, wo_h, wo_l);

    dim3 gProj(DM/128, MTOK/128);   // (8, 32)
    gemm_h3<<<gProj, 256, GEMM_SMEM>>>(qi_h, qi_l, wq_h, wq_l, bq, nullptr,
                                       SCALE_L2E, qh_h, qh_l, nullptr, MTOK, DM, DM);
    gemm_h3<<<gProj, 256, GEMM_SMEM>>>(ki_h, ki_l, wk_h, wk_l, bk, nullptr,
                                       1.0f, kh_h, kh_l, nullptr, MTOK, DM, DM);
    gemm_h3<<<gProj, 256, GEMM_SMEM>>>(vi_h, vi_l, wv_h, wv_l, bv, nullptr,
                                       1.0f, vh_h, nullptr, nullptr, MTOK, DM, DM);

    dim3 gA(Ss/32, Bb*Hh);          // (64, 32)
    attn_single<<<gA, 256, SMEM_ATTN>>>(attn);

    gemm_h3<<<gProj, 256, GEMM_SMEM>>>(oh_h, oh_l, wo_h, wo_l, bo, q,
                                       1.0f, nullptr, nullptr, y, MTOK, DM, DM);

    layernorm<<<MTOK, 256>>>(y, ln_g, ln_b, outp);
}

// round 9
// speedup vs baseline: 1.3390x; 1.3390x over previous
#include <cuda_runtime.h>
#include <cuda_fp16.h>
#include <math.h>

// Problem constants
#define Bb 2
#define Ss 2048
#define DM 1024
#define Hh 16
#define DKh 64
#define MTOK (Bb*Ss)                 // 4096
#define NROWS (Bb*Hh*Ss)             // 65536
#define OUT_ELEMS ((size_t)Bb*Ss*DM)

#define SCALE_L2E 0.18033688011112042f   // 0.125 * log2(e)

typedef unsigned int u32;
typedef unsigned short u16;
typedef unsigned long long u64;

// ---------------- device scratch ----------------
__device__ __half g_qi_h[MTOK*DM], g_qi_l[MTOK*DM];
__device__ __half g_ki_h[MTOK*DM], g_ki_l[MTOK*DM];
__device__ __half g_vi_h[MTOK*DM], g_vi_l[MTOK*DM];
__device__ __half g_wq_h[DM*DM], g_wq_l[DM*DM];
__device__ __half g_wk_h[DM*DM], g_wk_l[DM*DM];
__device__ __half g_wv_h[DM*DM], g_wv_l[DM*DM];
__device__ __half g_wo_h[DM*DM], g_wo_l[DM*DM];
__device__ __half g_qh_h[MTOK*DM], g_qh_l[MTOK*DM];
__device__ __half g_kh_h[MTOK*DM];
__device__ __half g_vh_h[MTOK*DM];
__device__ __half g_oh_h[MTOK*DM], g_oh_l[MTOK*DM];
__device__ float  g_y[MTOK*DM];
__device__ float  g_rinv[NROWS];
__device__ u64    g_mbits[(size_t)Bb*Ss*(Ss/64)];   // 1 bit per mask byte

// ---------------- helpers ----------------
__device__ __forceinline__ u32 smaddr(const void* p) {
    return (u32)__cvta_generic_to_shared(p);
}
__device__ __forceinline__ void ldsm4(u32& r0, u32& r1, u32& r2, u32& r3, u32 a) {
    asm volatile("ldmatrix.sync.aligned.m8n8.x4.shared.b16 {%0,%1,%2,%3},[%4];"
                 : "=r"(r0), "=r"(r1), "=r"(r2), "=r"(r3) : "r"(a));
}
__device__ __forceinline__ void ldsm4t(u32& r0, u32& r1, u32& r2, u32& r3, u32 a) {
    asm volatile("ldmatrix.sync.aligned.m8n8.x4.trans.shared.b16 {%0,%1,%2,%3},[%4];"
                 : "=r"(r0), "=r"(r1), "=r"(r2), "=r"(r3) : "r"(a));
}
__device__ __forceinline__ void mma16(float* d, const u32* a, u32 b0, u32 b1) {
    asm volatile(
        "mma.sync.aligned.m16n8k16.row.col.f32.f16.f16.f32 "
        "{%0,%1,%2,%3},{%4,%5,%6,%7},{%8,%9},{%0,%1,%2,%3};"
        : "+f"(d[0]), "+f"(d[1]), "+f"(d[2]), "+f"(d[3])
        : "r"(a[0]), "r"(a[1]), "r"(a[2]), "r"(a[3]), "r"(b0), "r"(b1));
}
__device__ __forceinline__ void cpa16(u32 dst, const void* src) {
    asm volatile("cp.async.cg.shared.global [%0], [%1], 16;" :: "r"(dst), "l"(src));
}
#define CP_COMMIT() asm volatile("cp.async.commit_group;")
#define CP_WAIT1()  asm volatile("cp.async.wait_group 1;")
#define CP_WAIT0()  asm volatile("cp.async.wait_group 0;")
__device__ __forceinline__ float ex2f(float x) {
    float r; asm("ex2.approx.f32 %0, %1;" : "=f"(r) : "f"(x)); return r;
}

// ---------------- mask -> bitmask (1 bit per byte) ----------------
__global__ void __launch_bounds__(256)
mask_bits(const unsigned char* __restrict__ mask)
{
    int i = blockIdx.x * 256 + threadIdx.x;       // < Bb*Ss*32
    const u64* src = (const u64*)(mask + (size_t)i * 64);
    u64 bits = 0;
    #pragma unroll
    for (int c = 0; c < 8; ++c) {
        u64 w = src[c] & 0x0101010101010101ULL;
        bits |= ((w * 0x0102040810204080ULL) >> 56) << (c * 8);
    }
    g_mbits[i] = bits;
}

// ---------------- split kernels ----------------
__global__ void __launch_bounds__(256)
split_f32(const float* __restrict__ src, __half* __restrict__ dh,
          __half* __restrict__ dl, int n4)
{
    int i = blockIdx.x * 256 + threadIdx.x;
    if (i >= n4) return;
    float4 v = ((const float4*)src)[i];
    __half2 h0 = __floats2half2_rn(v.x, v.y);
    __half2 h1 = __floats2half2_rn(v.z, v.w);
    float2 f0 = __half22float2(h0), f1 = __half22float2(h1);
    ((__half2*)dh)[2*i]   = h0; ((__half2*)dh)[2*i+1] = h1;
    ((__half2*)dl)[2*i]   = __floats2half2_rn(v.x - f0.x, v.y - f0.y);
    ((__half2*)dl)[2*i+1] = __floats2half2_rn(v.z - f1.x, v.w - f1.y);
}

// W[K][N] -> T[N][K] split hi/lo
__global__ void __launch_bounds__(256)
splitT_w(const float* __restrict__ W, __half* __restrict__ th,
         __half* __restrict__ tl)
{
    __shared__ float t[32][33];
    int kb = blockIdx.y * 32, nb = blockIdx.x * 32;
    int tx = threadIdx.x, ty = threadIdx.y;
    #pragma unroll
    for (int i = 0; i < 4; ++i)
        t[ty + i*8][tx] = W[(size_t)(kb + ty + i*8) * DM + nb + tx];
    __syncthreads();
    #pragma unroll
    for (int i = 0; i < 4; ++i) {
        int n = nb + ty + i*8, k = kb + tx;
        float v = t[tx][ty + i*8];
        __half h = __float2half_rn(v);
        th[(size_t)n * DM + k] = h;
        tl[(size_t)n * DM + k] = __float2half_rn(v - __half2float(h));
    }
}

// ---------------------------------------------------------------------------
// fp16 GEMM, cp.async double-buffered. Terms: ah.bh + al.bh (+ ah.bl if use_bl)
// ---------------------------------------------------------------------------
#define SG 40
#define GARR (128*SG)
#define GSTG (4*GARR)
__global__ void __launch_bounds__(256)
gemm_h3(const __half* __restrict__ Ah, const __half* __restrict__ Al,
        const __half* __restrict__ Bh, const __half* __restrict__ Bl,
        const float* __restrict__ bias, const float* __restrict__ R,
        float omul, int use_bl,
        __half* __restrict__ Ch, __half* __restrict__ Cl,
        float* __restrict__ Cf, int M, int N, int K)
{
    extern __shared__ __half dsm[];
    const int tid = threadIdx.x, lane = tid & 31, wid = tid >> 5;
    const int wm = wid & 3, wn = wid >> 2;
    const int bm = blockIdx.y * 128, bn = blockIdx.x * 128;
    float acc[2][8][4] = {};
    const int arow = lane & 15, achk = lane >> 4;
    const int brow = ((lane >> 4) << 3) + (lane & 7), bchk = (lane >> 3) & 1;
    const u32 smbase = smaddr(dsm);

    auto load_stage = [&](int st, int k0) {
        u32 base = smbase + (u32)st * GSTG * 2;
        #pragma unroll
        for (int i = 0; i < 2; ++i) {
            int e = tid + i * 256;
            int m = e >> 2, c = e & 3;
            size_t ga = (size_t)(bm + m) * K + k0 + c*8;
            size_t gb = (size_t)(bn + m) * K + k0 + c*8;
            u32 o = (u32)(m*SG + c*8) * 2;
            cpa16(base + 0*GARR*2 + o, Ah + ga);
            cpa16(base + 1*GARR*2 + o, Al + ga);
            cpa16(base + 2*GARR*2 + o, Bh + gb);
            if (use_bl) cpa16(base + 3*GARR*2 + o, Bl + gb);
        }
        CP_COMMIT();
    };

    const int nk = K / 32;
    load_stage(0, 0);
    for (int kt = 0; kt < nk; ++kt) {
        if (kt + 1 < nk) { load_stage((kt+1)&1, (kt+1)*32); CP_WAIT1(); }
        else             { CP_WAIT0(); }
        __syncthreads();
        const u32 sAh = smbase + (u32)(kt&1)*GSTG*2;
        const u32 sAl = sAh + GARR*2;
        const u32 sBh = sAl + GARR*2;
        const u32 sBl = sBh + GARR*2;
        #pragma unroll
        for (int kc = 0; kc < 2; ++kc) {
            u32 ah[2][4], al[2][4];
            #pragma unroll
            for (int mt = 0; mt < 2; ++mt) {
                int row = wm*32 + mt*16 + arow;
                u32 off = row*(SG*2) + (2*kc + achk)*16;
                ldsm4(ah[mt][0],ah[mt][1],ah[mt][2],ah[mt][3], sAh+off);
                ldsm4(al[mt][0],al[mt][1],al[mt][2],al[mt][3], sAl+off);
            }
            #pragma unroll
            for (int ntp = 0; ntp < 4; ++ntp) {
                int row = wn*64 + ntp*16 + brow;
                u32 off = row*(SG*2) + (2*kc + bchk)*16;
                u32 b0,b1,b2,b3;
                ldsm4(b0,b1,b2,b3, sBh+off);
                #pragma unroll
                for (int mt = 0; mt < 2; ++mt) {
                    mma16(acc[mt][2*ntp],   ah[mt], b0, b1);
                    mma16(acc[mt][2*ntp],   al[mt], b0, b1);
                    mma16(acc[mt][2*ntp+1], ah[mt], b2, b3);
                    mma16(acc[mt][2*ntp+1], al[mt], b2, b3);
                }
                if (use_bl) {
                    u32 c0,c1,c2,c3;
                    ldsm4(c0,c1,c2,c3, sBl+off);
                    #pragma unroll
                    for (int mt = 0; mt < 2; ++mt) {
                        mma16(acc[mt][2*ntp],   ah[mt], c0, c1);
                        mma16(acc[mt][2*ntp+1], ah[mt], c2, c3);
                    }
                }
            }
        }
        __syncthreads();
    }

    #pragma unroll
    for (int mt = 0; mt < 2; ++mt) {
        int r0 = bm + wm*32 + mt*16 + (lane >> 2);
        #pragma unroll
        for (int nt = 0; nt < 8; ++nt) {
            int n = bn + wn*64 + nt*8 + (lane & 3)*2;
            float2 bs = *(const float2*)&bias[n];
            float* d = acc[mt][nt];
            float v00 = (d[0]+bs.x)*omul, v01 = (d[1]+bs.y)*omul;
            float v10 = (d[2]+bs.x)*omul, v11 = (d[3]+bs.y)*omul;
            if (Cf) {
                float2 ra = *(const float2*)&R[(size_t)r0*N + n];
                float2 rb = *(const float2*)&R[(size_t)(r0+8)*N + n];
                *(float2*)&Cf[(size_t)r0*N + n]     = make_float2(v00+ra.x, v01+ra.y);
                *(float2*)&Cf[(size_t)(r0+8)*N + n] = make_float2(v10+rb.x, v11+rb.y);
            } else if (Cl) {
                __half2 h0 = __floats2half2_rn(v00, v01);
                __half2 h1 = __floats2half2_rn(v10, v11);
                float2 f0 = __half22float2(h0), f1 = __half22float2(h1);
                *(__half2*)&Ch[(size_t)r0*N + n]     = h0;
                *(__half2*)&Ch[(size_t)(r0+8)*N + n] = h1;
                *(__half2*)&Cl[(size_t)r0*N + n]     = __floats2half2_rn(v00-f0.x, v01-f0.y);
                *(__half2*)&Cl[(size_t)(r0+8)*N + n] = __floats2half2_rn(v10-f1.x, v11-f1.y);
            } else {
                *(__half2*)&Ch[(size_t)r0*N + n]     = __floats2half2_rn(v00, v01);
                *(__half2*)&Ch[(size_t)(r0+8)*N + n] = __floats2half2_rn(v10, v11);
            }
        }
    }
}

// ---------------------------------------------------------------------------
// Pass 1: row sums of 2^((qh+ql).kh) (masked). K hi-only staging.
// ---------------------------------------------------------------------------
#define SP 72
__global__ void __launch_bounds__(256)
attn_pass1()
{
    __shared__ __half sK[2][64*SP];
    const int tid = threadIdx.x, lane = tid & 31, wid = tid >> 5;
    const int bh = blockIdx.y, b = bh >> 4, h = bh & 15;
    const int bq = blockIdx.x * 128;
    const int arow = lane & 15, achk = lane >> 4;
    const int brow = ((lane >> 4) << 3) + (lane & 7), bchk = (lane >> 3) & 1;

    // Q fragments (hi in sK[0], lo in sK[1] staging)
    u32 qfh[4][4], qfl[4][4];
    #pragma unroll
    for (int c = 0; c < 2; ++c) {
        #pragma unroll
        for (int i = 0; i < 2; ++i) {
            int e = tid + i * 256;
            int m = e >> 3, ch = e & 7;
            size_t gq = (size_t)(b*Ss + bq + c*64 + m)*DM + h*DKh + ch*8;
            *(uint4*)&sK[0][m*SP + ch*8] = *(const uint4*)&g_qh_h[gq];
            *(uint4*)&sK[1][m*SP + ch*8] = *(const uint4*)&g_qh_l[gq];
        }
        __syncthreads();
        if ((wid >> 2) == c) {
            int rloc = (wid & 3)*16 + arow;
            #pragma unroll
            for (int kc = 0; kc < 4; ++kc) {
                u32 off = rloc*(SP*2) + (2*kc + achk)*16;
                ldsm4(qfh[kc][0],qfh[kc][1],qfh[kc][2],qfh[kc][3], smaddr(sK[0])+off);
                ldsm4(qfl[kc][0],qfl[kc][1],qfl[kc][2],qfl[kc][3], smaddr(sK[1])+off);
            }
        }
        __syncthreads();
    }

    auto load_stage = [&](int st, int kt) {
        #pragma unroll
        for (int i = 0; i < 2; ++i) {
            int e = tid + i * 256;
            int m = e >> 3, ch = e & 7;
            size_t gk = (size_t)(b*Ss + kt*64 + m)*DM + h*DKh + ch*8;
            cpa16(smaddr(sK[st]) + (u32)(m*SP + ch*8)*2, g_kh_h + gk);
        }
        CP_COMMIT();
    };

    const int r0 = bq + wid*16 + (lane >> 2);
    float rs0 = 0.f, rs1 = 0.f;

    load_stage(0, 0);
    for (int kt = 0; kt < 32; ++kt) {
        if (kt + 1 < 32) { load_stage((kt+1)&1, kt+1); CP_WAIT1(); }
        else             { CP_WAIT0(); }
        __syncthreads();
        const u32 sKh = smaddr(sK[kt&1]);

        float sf[8][4] = {};
        #pragma unroll
        for (int kc = 0; kc < 4; ++kc) {
            #pragma unroll
            for (int ntp = 0; ntp < 4; ++ntp) {
                int row = ntp*16 + brow;
                u32 off = row*(SP*2) + (2*kc + bchk)*16;
                u32 b0,b1,b2,b3;
                ldsm4(b0,b1,b2,b3, sKh+off);
                mma16(sf[2*ntp],   qfh[kc], b0, b1);
                mma16(sf[2*ntp],   qfl[kc], b0, b1);
                mma16(sf[2*ntp+1], qfh[kc], b2, b3);
                mma16(sf[2*ntp+1], qfl[kc], b2, b3);
            }
        }
        u64 mb0 = g_mbits[((size_t)b*Ss + r0)*32 + kt];
        u64 mb1 = g_mbits[((size_t)b*Ss + r0 + 8)*32 + kt];
        #pragma unroll
        for (int nt = 0; nt < 8; ++nt) {
            int sh = nt*8 + (lane & 3)*2;
            if (!((mb0 >> sh)     & 1)) rs0 += ex2f(sf[nt][0]);
            if (!((mb0 >> (sh+1)) & 1)) rs0 += ex2f(sf[nt][1]);
            if (!((mb1 >> sh)     & 1)) rs1 += ex2f(sf[nt][2]);
            if (!((mb1 >> (sh+1)) & 1)) rs1 += ex2f(sf[nt][3]);
        }
        __syncthreads();
    }

    rs0 += __shfl_xor_sync(0xffffffffu, rs0, 1);
    rs0 += __shfl_xor_sync(0xffffffffu, rs0, 2);
    rs1 += __shfl_xor_sync(0xffffffffu, rs1, 1);
    rs1 += __shfl_xor_sync(0xffffffffu, rs1, 2);
    if ((lane & 3) == 0) {
        g_rinv[(size_t)bh*Ss + r0]     = 1.0f / rs0;
        g_rinv[(size_t)bh*Ss + r0 + 8] = 1.0f / rs1;
    }
}

// ---------------------------------------------------------------------------
// Pass 2: S = (qh+ql).kh, p = 2^s*inv -> attn write; PV = p16 @ Vh fused.
// ---------------------------------------------------------------------------
__global__ void __launch_bounds__(256)
attn_pass2(float* __restrict__ P)
{
    __shared__ __half sKV[2][2][64*SP];   // [stage][K/V]
    const int tid = threadIdx.x, lane = tid & 31, wid = tid >> 5;
    const int bh = blockIdx.y, b = bh >> 4, h = bh & 15;
    const int bq = blockIdx.x * 128;
    const int arow = lane & 15, achk = lane >> 4;
    const int brow = ((lane >> 4) << 3) + (lane & 7), bchk = (lane >> 3) & 1;

    // Q fragments (stage via sKV[0][0]/sKV[0][1])
    u32 qfh[4][4], qfl[4][4];
    #pragma unroll
    for (int c = 0; c < 2; ++c) {
        #pragma unroll
        for (int i = 0; i < 2; ++i) {
            int e = tid + i * 256;
            int m = e >> 3, ch = e & 7;
            size_t gq = (size_t)(b*Ss + bq + c*64 + m)*DM + h*DKh + ch*8;
            *(uint4*)&sKV[0][0][m*SP + ch*8] = *(const uint4*)&g_qh_h[gq];
            *(uint4*)&sKV[0][1][m*SP + ch*8] = *(const uint4*)&g_qh_l[gq];
        }
        __syncthreads();
        if ((wid >> 2) == c) {
            int rloc = (wid & 3)*16 + arow;
            #pragma unroll
            for (int kc = 0; kc < 4; ++kc) {
                u32 off = rloc*(SP*2) + (2*kc + achk)*16;
                ldsm4(qfh[kc][0],qfh[kc][1],qfh[kc][2],qfh[kc][3], smaddr(sKV[0][0])+off);
                ldsm4(qfl[kc][0],qfl[kc][1],qfl[kc][2],qfl[kc][3], smaddr(sKV[0][1])+off);
            }
        }
        __syncthreads();
    }

    auto load_stage = [&](int st, int kt) {
        #pragma unroll
        for (int i = 0; i < 2; ++i) {
            int e = tid + i * 256;
            int m = e >> 3, ch = e & 7;
            size_t gk = (size_t)(b*Ss + kt*64 + m)*DM + h*DKh + ch*8;
            u32 o = (u32)(m*SP + ch*8)*2;
            cpa16(smaddr(sKV[st][0]) + o, g_kh_h + gk);
            cpa16(smaddr(sKV[st][1]) + o, g_vh_h + gk);
        }
        CP_COMMIT();
    };

    const int r0 = bq + wid*16 + (lane >> 2);
    const float inv0 = g_rinv[(size_t)bh*Ss + r0];
    const float inv1 = g_rinv[(size_t)bh*Ss + r0 + 8];
    float oacc[8][4] = {};

    load_stage(0, 0);
    for (int kt = 0; kt < 32; ++kt) {
        if (kt + 1 < 32) { load_stage((kt+1)&1, kt+1); CP_WAIT1(); }
        else             { CP_WAIT0(); }
        __syncthreads();
        const u32 sKh = smaddr(sKV[kt&1][0]);
        const u32 sVh = smaddr(sKV[kt&1][1]);

        // S = (qh+ql).kh
        float sf[8][4] = {};
        #pragma unroll
        for (int kc = 0; kc < 4; ++kc) {
            #pragma unroll
            for (int ntp = 0; ntp < 4; ++ntp) {
                int row = ntp*16 + brow;
                u32 off = row*(SP*2) + (2*kc + bchk)*16;
                u32 b0,b1,b2,b3;
                ldsm4(b0,b1,b2,b3, sKh+off);
                mma16(sf[2*ntp],   qfh[kc], b0, b1);
                mma16(sf[2*ntp],   qfl[kc], b0, b1);
                mma16(sf[2*ntp+1], qfh[kc], b2, b3);
                mma16(sf[2*ntp+1], qfl[kc], b2, b3);
            }
        }

        // p = 2^s * inv (masked), write final attn
        u64 mb0 = g_mbits[((size_t)b*Ss + r0)*32 + kt];
        u64 mb1 = g_mbits[((size_t)b*Ss + r0 + 8)*32 + kt];
        #pragma unroll
        for (int nt = 0; nt < 8; ++nt) {
            int sh = nt*8 + (lane & 3)*2;
            int col = kt*64 + sh;
            float p0 = ((mb0 >> sh)     & 1) ? 0.f : ex2f(sf[nt][0]) * inv0;
            float p1 = ((mb0 >> (sh+1)) & 1) ? 0.f : ex2f(sf[nt][1]) * inv0;
            float p2 = ((mb1 >> sh)     & 1) ? 0.f : ex2f(sf[nt][2]) * inv1;
            float p3 = ((mb1 >> (sh+1)) & 1) ? 0.f : ex2f(sf[nt][3]) * inv1;
            *(float2*)&P[((size_t)bh*Ss + r0)*Ss + col]     = make_float2(p0, p1);
            *(float2*)&P[((size_t)bh*Ss + r0 + 8)*Ss + col] = make_float2(p2, p3);
            sf[nt][0] = p0; sf[nt][1] = p1; sf[nt][2] = p2; sf[nt][3] = p3;
        }

        // PV: O += p16 @ Vh
        #pragma unroll
        for (int kc2 = 0; kc2 < 4; ++kc2) {
            u32 aph[4];
            #pragma unroll
            for (int half_ = 0; half_ < 2; ++half_) {
                float* f = sf[2*kc2 + half_];
                __half2 h0 = __floats2half2_rn(f[0], f[1]);
                __half2 h1 = __floats2half2_rn(f[2], f[3]);
                aph[2*half_]   = *(u32*)&h0;
                aph[2*half_+1] = *(u32*)&h1;
            }
            #pragma unroll
            for (int ntv = 0; ntv < 4; ++ntv) {
                int vrow = kc2*16 + ((lane >> 3) & 1)*8 + (lane & 7);
                int dch  = ntv*16 + (lane >> 4)*8;
                u32 off = vrow*(SP*2) + dch*2;
                u32 b0,b1,b2,b3;
                ldsm4t(b0,b1,b2,b3, sVh+off);
                mma16(oacc[2*ntv],   aph, b0, b1);
                mma16(oacc[2*ntv+1], aph, b2, b3);
            }
        }
        __syncthreads();
    }

    #pragma unroll
    for (int nt = 0; nt < 8; ++nt) {
        int d = nt*8 + (lane & 3)*2;
        size_t i0 = (size_t)(b*Ss + r0)*DM + h*DKh + d;
        size_t i1 = (size_t)(b*Ss + r0 + 8)*DM + h*DKh + d;
        __half2 h0 = __floats2half2_rn(oacc[nt][0], oacc[nt][1]);
        __half2 h1 = __floats2half2_rn(oacc[nt][2], oacc[nt][3]);
        float2 f0 = __half22float2(h0), f1 = __half22float2(h1);
        *(__half2*)&g_oh_h[i0] = h0;
        *(__half2*)&g_oh_h[i1] = h1;
        *(__half2*)&g_oh_l[i0] = __floats2half2_rn(oacc[nt][0]-f0.x, oacc[nt][1]-f0.y);
        *(__half2*)&g_oh_l[i1] = __floats2half2_rn(oacc[nt][2]-f1.x, oacc[nt][3]-f1.y);
    }
}

// ---------------------------------------------------------------------------
// LayerNorm per row of 1024
// ---------------------------------------------------------------------------
__global__ void __launch_bounds__(256)
layernorm(const float* __restrict__ Xin, const float* __restrict__ gamma,
          const float* __restrict__ beta, float* __restrict__ out)
{
    const float* x = Xin + (size_t)blockIdx.x * DM;
    float* o = out + (size_t)blockIdx.x * DM;
    const int tid = threadIdx.x;
    __shared__ float r1[256], r2[256];

    float v[4], s = 0.f, sq = 0.f;
    #pragma unroll
    for (int i = 0; i < 4; ++i) {
        v[i] = x[tid + i * 256];
        s += v[i];
        sq += v[i] * v[i];
    }
    r1[tid] = s; r2[tid] = sq; __syncthreads();
    for (int st = 128; st > 0; st >>= 1) {
        if (tid < st) { r1[tid] += r1[tid + st]; r2[tid] += r2[tid + st]; }
        __syncthreads();
    }
    float mean = r1[0] * (1.0f / DM);
    float var  = r2[0] * (1.0f / DM) - mean * mean;
    float inv = rsqrtf(var + 1e-5f);
    #pragma unroll
    for (int i = 0; i < 4; ++i) {
        int c = tid + i * 256;
        o[c] = (v[i] - mean) * inv * gamma[c] + beta[c];
    }
}

// ---------------------------------------------------------------------------
extern "C" void kernel_launch(void* const* d_in, const int* in_sizes, int n_in,
                              void* d_out, int out_size)
{
    const float* q    = (const float*)d_in[0];
    const float* k    = (const float*)d_in[1];
    const float* v    = (const float*)d_in[2];
    const unsigned char* mask = (const unsigned char*)d_in[3];
    const float* Wq   = (const float*)d_in[4];
    const float* bq   = (const float*)d_in[5];
    const float* Wk   = (const float*)d_in[6];
    const float* bk   = (const float*)d_in[7];
    const float* Wv   = (const float*)d_in[8];
    const float* bv   = (const float*)d_in[9];
    const float* Wo   = (const float*)d_in[10];
    const float* bo   = (const float*)d_in[11];
    const float* ln_g = (const float*)d_in[12];
    const float* ln_b = (const float*)d_in[13];

    float* outp = (float*)d_out;
    float* attn = outp + OUT_ELEMS;

    __half *qi_h,*qi_l,*ki_h,*ki_l,*vi_h,*vi_l;
    __half *wq_h,*wq_l,*wk_h,*wk_l,*wv_h,*wv_l,*wo_h,*wo_l;
    __half *qh_h,*qh_l,*kh_h,*vh_h,*oh_h,*oh_l;
    float *y;
    cudaGetSymbolAddress((void**)&qi_h, g_qi_h); cudaGetSymbolAddress((void**)&qi_l, g_qi_l);
    cudaGetSymbolAddress((void**)&ki_h, g_ki_h); cudaGetSymbolAddress((void**)&ki_l, g_ki_l);
    cudaGetSymbolAddress((void**)&vi_h, g_vi_h); cudaGetSymbolAddress((void**)&vi_l, g_vi_l);
    cudaGetSymbolAddress((void**)&wq_h, g_wq_h); cudaGetSymbolAddress((void**)&wq_l, g_wq_l);
    cudaGetSymbolAddress((void**)&wk_h, g_wk_h); cudaGetSymbolAddress((void**)&wk_l, g_wk_l);
    cudaGetSymbolAddress((void**)&wv_h, g_wv_h); cudaGetSymbolAddress((void**)&wv_l, g_wv_l);
    cudaGetSymbolAddress((void**)&wo_h, g_wo_h); cudaGetSymbolAddress((void**)&wo_l, g_wo_l);
    cudaGetSymbolAddress((void**)&qh_h, g_qh_h); cudaGetSymbolAddress((void**)&qh_l, g_qh_l);
    cudaGetSymbolAddress((void**)&kh_h, g_kh_h);
    cudaGetSymbolAddress((void**)&vh_h, g_vh_h);
    cudaGetSymbolAddress((void**)&oh_h, g_oh_h); cudaGetSymbolAddress((void**)&oh_l, g_oh_l);
    cudaGetSymbolAddress((void**)&y, g_y);

    static bool attr_done = false;
    const int GEMM_SMEM = 2 * GSTG * 2;
    if (!attr_done) {
        cudaFuncSetAttribute(gemm_h3, cudaFuncAttributeMaxDynamicSharedMemorySize, GEMM_SMEM);
        attr_done = true;
    }

    const int n4 = MTOK * DM / 4;
    split_f32<<<(n4+255)/256, 256>>>(q, qi_h, qi_l, n4);
    split_f32<<<(n4+255)/256, 256>>>(k, ki_h, ki_l, n4);
    split_f32<<<(n4+255)/256, 256>>>(v, vi_h, vi_l, n4);
    mask_bits<<<(Bb*Ss*32)/256, 256>>>(mask);

    dim3 gT(DM/32, DM/32), bT(32, 8);
    splitT_w<<<gT, bT>>>(Wq, wq_h, wq_l);
    splitT_w<<<gT, bT>>>(Wk, wk_h, wk_l);
    splitT_w<<<gT, bT>>>(Wv, wv_h, wv_l);
    splitT_w<<<gT, bT>>>(Wo, wo_h, wo_l);

    dim3 gProj(DM/128, MTOK/128);   // (8, 32)
    // Q: 3-term (lo feeds the ql.kh QK term)
    gemm_h3<<<gProj, 256, GEMM_SMEM>>>(qi_h, qi_l, wq_h, wq_l, bq, nullptr,
                                       SCALE_L2E, 1, qh_h, qh_l, nullptr, MTOK, DM, DM);
    // K: 2-term, hi-only output (kh_l is never consumed)
    gemm_h3<<<gProj, 256, GEMM_SMEM>>>(ki_h, ki_l, wk_h, wk_l, bk, nullptr,
                                       1.0f, 0, kh_h, nullptr, nullptr, MTOK, DM, DM);
    // V: 2-term, hi-only output
    gemm_h3<<<gProj, 256, GEMM_SMEM>>>(vi_h, vi_l, wv_h, wv_l, bv, nullptr,
                                       1.0f, 0, vh_h, nullptr, nullptr, MTOK, DM, DM);

    dim3 gAttn(Ss/128, Bb*Hh);      // (16, 32)
    attn_pass1<<<gAttn, 256>>>();
    attn_pass2<<<gAttn, 256>>>(attn);

    // Out-projection: 2-term (keeps ol.Wo_h, drops oh.Wo_l)
    gemm_h3<<<gProj, 256, GEMM_SMEM>>>(oh_h, oh_l, wo_h, wo_l, bo, q,
                                       1.0f, 0, nullptr, nullptr, y, MTOK, DM, DM);

    layernorm<<<MTOK, 256>>>(y, ln_g, ln_b, outp);
}